// round 4
// baseline (speedup 1.0000x reference)
#include <cuda_runtime.h>
#include <cstdint>

#define BATCH 8
#define SEQ   2048
#define EMB   1024
#define SCALE 0.03125f   // 1/sqrt(1024)

// ---------------- scratch (device globals; no allocation allowed) ----------
__device__ float g_Q[BATCH * SEQ * EMB];          // 64 MB
__device__ float g_K[BATCH * SEQ * EMB];          // 64 MB
__device__ float g_V[BATCH * SEQ * EMB];          // 64 MB
__device__ float g_S[(size_t)BATCH * SEQ * SEQ];  // 128 MB raw masked logits
__device__ float g_L[BATCH * SEQ];                // row sum of exp
__device__ int   g_mask_mode;                     // 1 = byte mask, 0 = int32 mask

// ---------------- helpers --------------------------------------------------
__device__ __forceinline__ uint32_t f2tf(float x) {
    uint32_t r;
    asm("cvt.rna.tf32.f32 %0, %1;" : "=r"(r) : "f"(x));
    return r;
}

__device__ __forceinline__ void mma_tf32(float acc[4], const uint32_t a[4], const uint32_t b[2]) {
    asm volatile(
        "mma.sync.aligned.m16n8k8.row.col.f32.tf32.tf32.f32 "
        "{%0,%1,%2,%3}, {%4,%5,%6,%7}, {%8,%9}, {%0,%1,%2,%3};\n"
        : "+f"(acc[0]), "+f"(acc[1]), "+f"(acc[2]), "+f"(acc[3])
        : "r"(a[0]), "r"(a[1]), "r"(a[2]), "r"(a[3]), "r"(b[0]), "r"(b[1]));
}

// split fp32 into tf32 hi/lo (both rna-rounded to valid tf32)
__device__ __forceinline__ void split_tf32(float v, float& hi, float& lo) {
    hi = __uint_as_float(f2tf(v));
    lo = __uint_as_float(f2tf(v - hi));
}

// ---------------- mask dtype probe -----------------------------------------
// bool mask may be serialized as 1-byte bools or int32. If bytes, some of the
// first 1024 words (4096 random bools) will exceed 1 with probability ~1.
__global__ void detect_mask_kernel(const unsigned int* __restrict__ m) {
    if (threadIdx.x == 0 && blockIdx.x == 0) {
        int bm = 0;
        for (int i = 0; i < 1024; ++i)
            if (m[i] > 1u) { bm = 1; break; }
        g_mask_mode = bm;
    }
}

// ---------------- kernel A: projection  C[M,N] = A[M,K] @ W[N,K]^T + bias ---
// M=16384, N=1024, K=1024. tf32x2 (3-pass) for fp32-level accuracy.
__global__ __launch_bounds__(256, 1)
void proj_kernel(const float* __restrict__ A, const float* __restrict__ W,
                 const float* __restrict__ bias, int which) {
    float* C = (which == 0) ? g_Q : (which == 1) ? g_K : g_V;

    __shared__ __align__(16) float As_hi[128][20], As_lo[128][20];
    __shared__ __align__(16) float Bs_hi[128][20], Bs_lo[128][20];

    const int tid  = threadIdx.x;
    const int warp = tid >> 5, lane = tid & 31;
    const int grp  = lane >> 2, qt = lane & 3;
    const int wm   = (warp >> 2) * 64;   // 2 warp rows
    const int wn   = (warp & 3) * 32;    // 4 warp cols
    const int m0   = blockIdx.y * 128, n0 = blockIdx.x * 128;

    float acc[4][4][4] = {};

    for (int kt = 0; kt < 64; ++kt) {
        const int k0 = kt * 16;
        __syncthreads();
        // stage A + W tiles, splitting to tf32 hi/lo
        #pragma unroll
        for (int it = 0; it < 2; ++it) {
            const int idx = tid + it * 256;
            const int row = idx >> 2, kq = (idx & 3) * 4;
            float4 va = *reinterpret_cast<const float4*>(A + (size_t)(m0 + row) * EMB + k0 + kq);
            float4 h, l;
            split_tf32(va.x, h.x, l.x); split_tf32(va.y, h.y, l.y);
            split_tf32(va.z, h.z, l.z); split_tf32(va.w, h.w, l.w);
            *reinterpret_cast<float4*>(&As_hi[row][kq]) = h;
            *reinterpret_cast<float4*>(&As_lo[row][kq]) = l;
            float4 vb = *reinterpret_cast<const float4*>(W + (size_t)(n0 + row) * EMB + k0 + kq);
            split_tf32(vb.x, h.x, l.x); split_tf32(vb.y, h.y, l.y);
            split_tf32(vb.z, h.z, l.z); split_tf32(vb.w, h.w, l.w);
            *reinterpret_cast<float4*>(&Bs_hi[row][kq]) = h;
            *reinterpret_cast<float4*>(&Bs_lo[row][kq]) = l;
        }
        __syncthreads();
        #pragma unroll
        for (int ks = 0; ks < 2; ++ks) {
            const int kb = ks * 8;
            uint32_t ah[4][4], al[4][4], bh[4][2], bl[4][2];
            #pragma unroll
            for (int mf = 0; mf < 4; ++mf) {
                const int r = wm + mf * 16 + grp;
                ah[mf][0] = __float_as_uint(As_hi[r][kb + qt]);
                ah[mf][1] = __float_as_uint(As_hi[r + 8][kb + qt]);
                ah[mf][2] = __float_as_uint(As_hi[r][kb + qt + 4]);
                ah[mf][3] = __float_as_uint(As_hi[r + 8][kb + qt + 4]);
                al[mf][0] = __float_as_uint(As_lo[r][kb + qt]);
                al[mf][1] = __float_as_uint(As_lo[r + 8][kb + qt]);
                al[mf][2] = __float_as_uint(As_lo[r][kb + qt + 4]);
                al[mf][3] = __float_as_uint(As_lo[r + 8][kb + qt + 4]);
            }
            #pragma unroll
            for (int nf = 0; nf < 4; ++nf) {
                const int n = wn + nf * 8 + grp;
                bh[nf][0] = __float_as_uint(Bs_hi[n][kb + qt]);
                bh[nf][1] = __float_as_uint(Bs_hi[n][kb + qt + 4]);
                bl[nf][0] = __float_as_uint(Bs_lo[n][kb + qt]);
                bl[nf][1] = __float_as_uint(Bs_lo[n][kb + qt + 4]);
            }
            #pragma unroll
            for (int mf = 0; mf < 4; ++mf)
                #pragma unroll
                for (int nf = 0; nf < 4; ++nf) {
                    mma_tf32(acc[mf][nf], ah[mf], bh[nf]);
                    mma_tf32(acc[mf][nf], al[mf], bh[nf]);
                    mma_tf32(acc[mf][nf], ah[mf], bl[nf]);
                }
        }
    }

    #pragma unroll
    for (int mf = 0; mf < 4; ++mf)
        #pragma unroll
        for (int nf = 0; nf < 4; ++nf) {
            const int r = m0 + wm + mf * 16 + grp;
            const int c = n0 + wn + nf * 8 + qt * 2;
            const float b0v = bias[c], b1v = bias[c + 1];
            *reinterpret_cast<float2*>(C + (size_t)r * EMB + c) =
                make_float2(acc[mf][nf][0] + b0v, acc[mf][nf][1] + b1v);
            *reinterpret_cast<float2*>(C + (size_t)(r + 8) * EMB + c) =
                make_float2(acc[mf][nf][2] + b0v, acc[mf][nf][3] + b1v);
        }
}

// ---------------- kernel B: logits + row sumexp -----------------------------
// CTA = (iblock of 128 query rows, batch). Loops all 16 j-tiles so the whole
// row's statistics stay CTA-local. tf32x2 QK^T. Writes raw masked logits.
__global__ __launch_bounds__(256, 1)
void logits_kernel(const void* __restrict__ maskp) {
    __shared__ __align__(16) float As_hi[128][20], As_lo[128][20];
    __shared__ __align__(16) float Bs_hi[128][20], Bs_lo[128][20];
    __shared__ float l_sm[128];

    const int tid  = threadIdx.x;
    const int warp = tid >> 5, lane = tid & 31;
    const int grp  = lane >> 2, qt = lane & 3;
    const int wm   = (warp >> 2) * 64;
    const int wn   = (warp & 3) * 32;
    const int ib   = blockIdx.x, b = blockIdx.y;
    const int i0   = ib * 128;
    const float* Qb = g_Q + (size_t)(b * SEQ + i0) * EMB;
    const float* Kb = g_K + (size_t)b * SEQ * EMB;
    const int byteMode = g_mask_mode;

    if (tid < 128) l_sm[tid] = 0.f;

    for (int jb = 0; jb < 16; ++jb) {
        const int j0 = jb * 128;
        float acc[4][4][4] = {};

        for (int kt = 0; kt < 64; ++kt) {
            const int k0 = kt * 16;
            __syncthreads();
            #pragma unroll
            for (int it = 0; it < 2; ++it) {
                const int idx = tid + it * 256;
                const int row = idx >> 2, kq = (idx & 3) * 4;
                float4 va = *reinterpret_cast<const float4*>(Qb + (size_t)row * EMB + k0 + kq);
                float4 h, l;
                split_tf32(va.x, h.x, l.x); split_tf32(va.y, h.y, l.y);
                split_tf32(va.z, h.z, l.z); split_tf32(va.w, h.w, l.w);
                *reinterpret_cast<float4*>(&As_hi[row][kq]) = h;
                *reinterpret_cast<float4*>(&As_lo[row][kq]) = l;
                float4 vb = *reinterpret_cast<const float4*>(Kb + (size_t)(j0 + row) * EMB + k0 + kq);
                split_tf32(vb.x, h.x, l.x); split_tf32(vb.y, h.y, l.y);
                split_tf32(vb.z, h.z, l.z); split_tf32(vb.w, h.w, l.w);
                *reinterpret_cast<float4*>(&Bs_hi[row][kq]) = h;
                *reinterpret_cast<float4*>(&Bs_lo[row][kq]) = l;
            }
            __syncthreads();
            #pragma unroll
            for (int ks = 0; ks < 2; ++ks) {
                const int kb = ks * 8;
                uint32_t ah[4][4], al[4][4], bh[4][2], bl[4][2];
                #pragma unroll
                for (int mf = 0; mf < 4; ++mf) {
                    const int r = wm + mf * 16 + grp;
                    ah[mf][0] = __float_as_uint(As_hi[r][kb + qt]);
                    ah[mf][1] = __float_as_uint(As_hi[r + 8][kb + qt]);
                    ah[mf][2] = __float_as_uint(As_hi[r][kb + qt + 4]);
                    ah[mf][3] = __float_as_uint(As_hi[r + 8][kb + qt + 4]);
                    al[mf][0] = __float_as_uint(As_lo[r][kb + qt]);
                    al[mf][1] = __float_as_uint(As_lo[r + 8][kb + qt]);
                    al[mf][2] = __float_as_uint(As_lo[r][kb + qt + 4]);
                    al[mf][3] = __float_as_uint(As_lo[r + 8][kb + qt + 4]);
                }
                #pragma unroll
                for (int nf = 0; nf < 4; ++nf) {
                    const int n = wn + nf * 8 + grp;
                    bh[nf][0] = __float_as_uint(Bs_hi[n][kb + qt]);
                    bh[nf][1] = __float_as_uint(Bs_hi[n][kb + qt + 4]);
                    bl[nf][0] = __float_as_uint(Bs_lo[n][kb + qt]);
                    bl[nf][1] = __float_as_uint(Bs_lo[n][kb + qt + 4]);
                }
                #pragma unroll
                for (int mf = 0; mf < 4; ++mf)
                    #pragma unroll
                    for (int nf = 0; nf < 4; ++nf) {
                        mma_tf32(acc[mf][nf], ah[mf], bh[nf]);
                        mma_tf32(acc[mf][nf], al[mf], bh[nf]);
                        mma_tf32(acc[mf][nf], ah[mf], bl[nf]);
                    }
            }
        }

        // epilogue: scale, mask, store raw logits, accumulate row sumexp
        #pragma unroll
        for (int mf = 0; mf < 4; ++mf) {
            #pragma unroll
            for (int h = 0; h < 2; ++h) {
                const int rl = wm + mf * 16 + h * 8 + grp;
                const size_t gi = (size_t)(b * SEQ + i0 + rl);
                float rs = 0.f;
                #pragma unroll
                for (int nf = 0; nf < 4; ++nf) {
                    const int gj = j0 + wn + nf * 8 + qt * 2;
                    float s0 = acc[mf][nf][h * 2]     * SCALE;
                    float s1 = acc[mf][nf][h * 2 + 1] * SCALE;
                    bool mk0, mk1;
                    if (byteMode) {
                        const unsigned char* mp = (const unsigned char*)maskp + gi * SEQ + gj;
                        mk0 = mp[0] != 0; mk1 = mp[1] != 0;
                    } else {
                        const int* mp = (const int*)maskp + gi * SEQ + gj;
                        mk0 = mp[0] != 0; mk1 = mp[1] != 0;
                    }
                    if (mk0) s0 = -1e9f;
                    if (mk1) s1 = -1e9f;
                    *reinterpret_cast<float2*>(g_S + gi * SEQ + gj) = make_float2(s0, s1);
                    rs += __expf(s0) + __expf(s1);
                }
                rs += __shfl_xor_sync(0xffffffffu, rs, 1);
                rs += __shfl_xor_sync(0xffffffffu, rs, 2);
                if (qt == 0) atomicAdd(&l_sm[rl], rs);
            }
        }
    }

    __syncthreads();
    if (tid < 128) g_L[(size_t)b * SEQ + i0 + tid] = l_sm[tid];
}

// ---------------- kernel C: out = P @ V, write normalized att ---------------
// CTA = (nchunk of 128 out cols, iblock of 128 rows, batch). nchunk 0 also
// writes the normalized attention matrix.
__global__ __launch_bounds__(256, 1)
void pv_kernel(float* __restrict__ out, float* __restrict__ att) {
    __shared__ __align__(16) float Ps[128][20];
    __shared__ __align__(16) float Vs[16][136];
    __shared__ float invl[128];

    const int tid  = threadIdx.x;
    const int warp = tid >> 5, lane = tid & 31;
    const int grp  = lane >> 2, qt = lane & 3;
    const int wm   = (warp >> 2) * 64;
    const int wn   = (warp & 3) * 32;
    const int nch  = blockIdx.x, ib = blockIdx.y, b = blockIdx.z;
    const int i0   = ib * 128, n0 = nch * 128;
    const bool writeAtt = (nch == 0);

    if (tid < 128) {
        const float l = g_L[(size_t)b * SEQ + i0 + tid];
        invl[tid] = (l > 0.f) ? (1.f / l) : 0.f;
    }

    float acc[4][4][4] = {};

    for (int jt = 0; jt < 128; ++jt) {
        const int j0 = jt * 16;
        __syncthreads();
        // stage P (exp + normalize + rna round); nchunk0 writes final att
        #pragma unroll
        for (int it = 0; it < 2; ++it) {
            const int idx = tid + it * 256;
            const int row = idx >> 2, kq = (idx & 3) * 4;
            const size_t off = (size_t)(b * SEQ + i0 + row) * SEQ + j0 + kq;
            float4 s4 = *reinterpret_cast<const float4*>(g_S + off);
            const float il = invl[row];
            float4 p;
            p.x = __expf(s4.x) * il; p.y = __expf(s4.y) * il;
            p.z = __expf(s4.z) * il; p.w = __expf(s4.w) * il;
            if (writeAtt) *reinterpret_cast<float4*>(att + off) = p;
            float4 pr;
            pr.x = __uint_as_float(f2tf(p.x)); pr.y = __uint_as_float(f2tf(p.y));
            pr.z = __uint_as_float(f2tf(p.z)); pr.w = __uint_as_float(f2tf(p.w));
            *reinterpret_cast<float4*>(&Ps[row][kq]) = pr;
        }
        // stage V (natural [k][n] layout, stride 136 -> conflict-free frags)
        #pragma unroll
        for (int it = 0; it < 2; ++it) {
            const int idx = tid + it * 256;
            const int k = idx >> 5, nq = (idx & 31) * 4;
            float4 v = *reinterpret_cast<const float4*>(
                g_V + (size_t)(b * SEQ + j0 + k) * EMB + n0 + nq);
            float4 vr;
            vr.x = __uint_as_float(f2tf(v.x)); vr.y = __uint_as_float(f2tf(v.y));
            vr.z = __uint_as_float(f2tf(v.z)); vr.w = __uint_as_float(f2tf(v.w));
            *reinterpret_cast<float4*>(&Vs[k][nq]) = vr;
        }
        __syncthreads();
        #pragma unroll
        for (int ks = 0; ks < 2; ++ks) {
            const int kb = ks * 8;
            uint32_t a[4][4], bb[4][2];
            #pragma unroll
            for (int mf = 0; mf < 4; ++mf) {
                const int r = wm + mf * 16 + grp;
                a[mf][0] = __float_as_uint(Ps[r][kb + qt]);
                a[mf][1] = __float_as_uint(Ps[r + 8][kb + qt]);
                a[mf][2] = __float_as_uint(Ps[r][kb + qt + 4]);
                a[mf][3] = __float_as_uint(Ps[r + 8][kb + qt + 4]);
            }
            #pragma unroll
            for (int nf = 0; nf < 4; ++nf) {
                const int n = wn + nf * 8 + grp;
                bb[nf][0] = __float_as_uint(Vs[kb + qt][n]);
                bb[nf][1] = __float_as_uint(Vs[kb + qt + 4][n]);
            }
            #pragma unroll
            for (int mf = 0; mf < 4; ++mf)
                #pragma unroll
                for (int nf = 0; nf < 4; ++nf)
                    mma_tf32(acc[mf][nf], a[mf], bb[nf]);
        }
    }

    #pragma unroll
    for (int mf = 0; mf < 4; ++mf)
        #pragma unroll
        for (int nf = 0; nf < 4; ++nf) {
            const int r = i0 + wm + mf * 16 + grp;
            const int c = n0 + wn + nf * 8 + qt * 2;
            *reinterpret_cast<float2*>(out + (size_t)(b * SEQ + r) * EMB + c) =
                make_float2(acc[mf][nf][0], acc[mf][nf][1]);
            *reinterpret_cast<float2*>(out + (size_t)(b * SEQ + r + 8) * EMB + c) =
                make_float2(acc[mf][nf][2], acc[mf][nf][3]);
        }
}

// ---------------- launch -----------------------------------------------------
extern "C" void kernel_launch(void* const* d_in, const int* in_sizes, int n_in,
                              void* d_out, int out_size) {
    const float* x    = (const float*)d_in[0];
    const float* ctx  = (const float*)d_in[1];
    const void*  mask = d_in[2];
    const float* Wq   = (const float*)d_in[3];
    const float* bq   = (const float*)d_in[4];
    const float* Wk   = (const float*)d_in[5];
    const float* bk   = (const float*)d_in[6];
    const float* Wv   = (const float*)d_in[7];
    const float* bv   = (const float*)d_in[8];

    float* out = (float*)d_out;
    float* att = out + (size_t)BATCH * SEQ * EMB;

    detect_mask_kernel<<<1, 32>>>((const unsigned int*)mask);

    dim3 gproj(EMB / 128, (BATCH * SEQ) / 128);   // (8, 128)
    proj_kernel<<<gproj, 256>>>(x,   Wq, bq, 0);
    proj_kernel<<<gproj, 256>>>(ctx, Wk, bk, 1);
    proj_kernel<<<gproj, 256>>>(ctx, Wv, bv, 2);

    logits_kernel<<<dim3(SEQ / 128, BATCH), 256>>>(mask);

    pv_kernel<<<dim3(EMB / 128, SEQ / 128, BATCH), 256>>>(out, att);
}

// round 9
// speedup vs baseline: 1.6978x; 1.6978x over previous
#include <cuda_runtime.h>
#include <cuda_bf16.h>
#include <cstdint>

#define BATCH 8
#define SEQ   2048
#define EMB   1024
#define SCALE 0.03125f   // 1/sqrt(1024)

// ---------------- scratch (device globals; no allocation allowed) ----------
__device__ __nv_bfloat16 g_Xhi[BATCH * SEQ * EMB], g_Xlo[BATCH * SEQ * EMB];
__device__ __nv_bfloat16 g_Chi[BATCH * SEQ * EMB], g_Clo[BATCH * SEQ * EMB];
__device__ __nv_bfloat16 g_Wqh[EMB * EMB], g_Wql[EMB * EMB];
__device__ __nv_bfloat16 g_Wkh[EMB * EMB], g_Wkl[EMB * EMB];
__device__ __nv_bfloat16 g_Wvh[EMB * EMB], g_Wvl[EMB * EMB];
__device__ __nv_bfloat16 g_Qhi[BATCH * SEQ * EMB], g_Qlo[BATCH * SEQ * EMB];
__device__ __nv_bfloat16 g_Khi[BATCH * SEQ * EMB], g_Klo[BATCH * SEQ * EMB];
__device__ float g_V[BATCH * SEQ * EMB];            // tf32-prerounded V
__device__ float g_S[(size_t)BATCH * SEQ * SEQ];    // tf32-prerounded exp(masked logits)
__device__ float g_L[BATCH * SEQ];                  // row sums of exp
__device__ int   g_mask_mode;

// ---------------- helpers --------------------------------------------------
__device__ __forceinline__ uint32_t f2tf(float x) {
    uint32_t r;
    asm("cvt.rna.tf32.f32 %0, %1;" : "=r"(r) : "f"(x));
    return r;
}

__device__ __forceinline__ void mma_tf32(float acc[4], const uint32_t a[4], const uint32_t b[2]) {
    asm volatile(
        "mma.sync.aligned.m16n8k8.row.col.f32.tf32.tf32.f32 "
        "{%0,%1,%2,%3}, {%4,%5,%6,%7}, {%8,%9}, {%0,%1,%2,%3};\n"
        : "+f"(acc[0]), "+f"(acc[1]), "+f"(acc[2]), "+f"(acc[3])
        : "r"(a[0]), "r"(a[1]), "r"(a[2]), "r"(a[3]), "r"(b[0]), "r"(b[1]));
}

__device__ __forceinline__ void mma_bf16(float acc[4], const uint32_t a[4], const uint32_t b[2]) {
    asm volatile(
        "mma.sync.aligned.m16n8k16.row.col.f32.bf16.bf16.f32 "
        "{%0,%1,%2,%3}, {%4,%5,%6,%7}, {%8,%9}, {%0,%1,%2,%3};\n"
        : "+f"(acc[0]), "+f"(acc[1]), "+f"(acc[2]), "+f"(acc[3])
        : "r"(a[0]), "r"(a[1]), "r"(a[2]), "r"(a[3]), "r"(b[0]), "r"(b[1]));
}

__device__ __forceinline__ void split_bf(float v, __nv_bfloat16& h, __nv_bfloat16& l) {
    h = __float2bfloat16_rn(v);
    l = __float2bfloat16_rn(v - __bfloat162float(h));
}

__device__ __forceinline__ uint32_t pack_bf2(__nv_bfloat16 a, __nv_bfloat16 b) {
    __nv_bfloat162 t = __halves2bfloat162(a, b);
    return *reinterpret_cast<uint32_t*>(&t);
}

__device__ __forceinline__ uint32_t smem_u32(const void* p) {
    return (uint32_t)__cvta_generic_to_shared(p);
}

#define CP16(dst, src) \
    asm volatile("cp.async.cg.shared.global [%0], [%1], 16;\n" :: "r"(dst), "l"(src))
#define CP_COMMIT() asm volatile("cp.async.commit_group;\n")
#define CP_WAIT0()  asm volatile("cp.async.wait_group 0;\n")

// ---------------- mask dtype probe -----------------------------------------
__global__ void detect_mask_kernel(const unsigned int* __restrict__ m) {
    if (threadIdx.x == 0 && blockIdx.x == 0) {
        int bm = 0;
        for (int i = 0; i < 1024; ++i)
            if (m[i] > 1u) { bm = 1; break; }
        g_mask_mode = bm;
    }
}

// ---------------- split inputs into bf16 hi/lo pairs -----------------------
// sel: 0=x, 1=context, 2=Wq, 3=Wk, 4=Wv
__global__ void split_kernel(const float* __restrict__ src, int sel, int n4) {
    int i = blockIdx.x * blockDim.x + threadIdx.x;
    if (i >= n4) return;
    __nv_bfloat16* hi;
    __nv_bfloat16* lo;
    switch (sel) {
        case 0:  hi = g_Xhi; lo = g_Xlo; break;
        case 1:  hi = g_Chi; lo = g_Clo; break;
        case 2:  hi = g_Wqh; lo = g_Wql; break;
        case 3:  hi = g_Wkh; lo = g_Wkl; break;
        default: hi = g_Wvh; lo = g_Wvl; break;
    }
    float4 v = reinterpret_cast<const float4*>(src)[i];
    __nv_bfloat16 h0, l0, h1, l1, h2, l2, h3, l3;
    split_bf(v.x, h0, l0); split_bf(v.y, h1, l1);
    split_bf(v.z, h2, l2); split_bf(v.w, h3, l3);
    uint2 hw = make_uint2(pack_bf2(h0, h1), pack_bf2(h2, h3));
    uint2 lw = make_uint2(pack_bf2(l0, l1), pack_bf2(l2, l3));
    reinterpret_cast<uint2*>(hi)[i] = hw;
    reinterpret_cast<uint2*>(lo)[i] = lw;
}

__global__ void zeroL_kernel() {
    g_L[blockIdx.x * blockDim.x + threadIdx.x] = 0.f;
}

// ---------------- kernel A: projection  C[M,N] = A[M,K] @ W[N,K]^T + bias ---
// bf16 hi/lo 3-pass, cp.async double-buffered.
// which: 0 -> Q (A=x),  1 -> K (A=ctx),  2 -> V (A=ctx, fp32 tf32-rounded out)
__global__ __launch_bounds__(256, 1)
void proj_kernel(const float* __restrict__ bias, int which) {
    __shared__ __align__(16) uint32_t Ah[2][128][12], Al[2][128][12];
    __shared__ __align__(16) uint32_t Bh[2][128][12], Bl[2][128][12];

    const int tid  = threadIdx.x;
    const int warp = tid >> 5, lane = tid & 31;
    const int grp  = lane >> 2, qt = lane & 3;
    const int wm   = (warp >> 2) * 64;
    const int wn   = (warp & 3) * 32;
    const int m0   = blockIdx.y * 128, n0 = blockIdx.x * 128;
    const int lrow = tid >> 1, lhalf = tid & 1;

    const __nv_bfloat16* Ahi_g = (which == 0) ? g_Xhi : g_Chi;
    const __nv_bfloat16* Alo_g = (which == 0) ? g_Xlo : g_Clo;
    const __nv_bfloat16* Bhi_g = (which == 0) ? g_Wqh : (which == 1) ? g_Wkh : g_Wvh;
    const __nv_bfloat16* Blo_g = (which == 0) ? g_Wql : (which == 1) ? g_Wkl : g_Wvl;

    const __nv_bfloat16* pa_h = Ahi_g + (size_t)(m0 + lrow) * EMB + lhalf * 8;
    const __nv_bfloat16* pa_l = Alo_g + (size_t)(m0 + lrow) * EMB + lhalf * 8;
    const __nv_bfloat16* pb_h = Bhi_g + (size_t)(n0 + lrow) * EMB + lhalf * 8;
    const __nv_bfloat16* pb_l = Blo_g + (size_t)(n0 + lrow) * EMB + lhalf * 8;

    const uint32_t sAh = smem_u32(&Ah[0][lrow][lhalf * 4]);
    const uint32_t sAl = smem_u32(&Al[0][lrow][lhalf * 4]);
    const uint32_t sBh = smem_u32(&Bh[0][lrow][lhalf * 4]);
    const uint32_t sBl = smem_u32(&Bl[0][lrow][lhalf * 4]);
    const uint32_t bstr = 128 * 12 * 4;

    float acc[4][4][4] = {};

    // prologue
    CP16(sAh, pa_h); CP16(sAl, pa_l); CP16(sBh, pb_h); CP16(sBl, pb_l);
    CP_COMMIT();

    for (int kt = 0; kt < 64; ++kt) {
        const int buf = kt & 1;
        CP_WAIT0();
        __syncthreads();
        if (kt < 63) {
            const int ko = (kt + 1) * 16;
            const uint32_t bo = (buf ^ 1) * bstr;
            CP16(sAh + bo, pa_h + ko); CP16(sAl + bo, pa_l + ko);
            CP16(sBh + bo, pb_h + ko); CP16(sBl + bo, pb_l + ko);
            CP_COMMIT();
        }
        uint32_t ah[4][4], al[4][4], bh[4][2], bl[4][2];
        #pragma unroll
        for (int mf = 0; mf < 4; ++mf) {
            const int r = wm + mf * 16 + grp;
            ah[mf][0] = Ah[buf][r][qt];     ah[mf][1] = Ah[buf][r + 8][qt];
            ah[mf][2] = Ah[buf][r][qt + 4]; ah[mf][3] = Ah[buf][r + 8][qt + 4];
            al[mf][0] = Al[buf][r][qt];     al[mf][1] = Al[buf][r + 8][qt];
            al[mf][2] = Al[buf][r][qt + 4]; al[mf][3] = Al[buf][r + 8][qt + 4];
        }
        #pragma unroll
        for (int nf = 0; nf < 4; ++nf) {
            const int n = wn + nf * 8 + grp;
            bh[nf][0] = Bh[buf][n][qt]; bh[nf][1] = Bh[buf][n][qt + 4];
            bl[nf][0] = Bl[buf][n][qt]; bl[nf][1] = Bl[buf][n][qt + 4];
        }
        #pragma unroll
        for (int mf = 0; mf < 4; ++mf)
            #pragma unroll
            for (int nf = 0; nf < 4; ++nf) {
                mma_bf16(acc[mf][nf], ah[mf], bh[nf]);
                mma_bf16(acc[mf][nf], al[mf], bh[nf]);
                mma_bf16(acc[mf][nf], ah[mf], bl[nf]);
            }
    }

    // epilogue
    if (which == 2) {
        #pragma unroll
        for (int mf = 0; mf < 4; ++mf)
            #pragma unroll
            for (int nf = 0; nf < 4; ++nf) {
                const int r = m0 + wm + mf * 16 + grp;
                const int c = n0 + wn + nf * 8 + qt * 2;
                const float b0v = bias[c], b1v = bias[c + 1];
                float2 v0 = make_float2(__uint_as_float(f2tf(acc[mf][nf][0] + b0v)),
                                        __uint_as_float(f2tf(acc[mf][nf][1] + b1v)));
                float2 v1 = make_float2(__uint_as_float(f2tf(acc[mf][nf][2] + b0v)),
                                        __uint_as_float(f2tf(acc[mf][nf][3] + b1v)));
                *reinterpret_cast<float2*>(g_V + (size_t)r * EMB + c) = v0;
                *reinterpret_cast<float2*>(g_V + (size_t)(r + 8) * EMB + c) = v1;
            }
    } else {
        __nv_bfloat16* Oh = (which == 0) ? g_Qhi : g_Khi;
        __nv_bfloat16* Ol = (which == 0) ? g_Qlo : g_Klo;
        #pragma unroll
        for (int mf = 0; mf < 4; ++mf)
            #pragma unroll
            for (int nf = 0; nf < 4; ++nf) {
                const int r = m0 + wm + mf * 16 + grp;
                const int c = n0 + wn + nf * 8 + qt * 2;
                const float b0v = bias[c], b1v = bias[c + 1];
                float v0 = acc[mf][nf][0] + b0v, v1 = acc[mf][nf][1] + b1v;
                float v2 = acc[mf][nf][2] + b0v, v3 = acc[mf][nf][3] + b1v;
                __nv_bfloat16 h0, l0, h1, l1;
                split_bf(v0, h0, l0); split_bf(v1, h1, l1);
                *reinterpret_cast<uint32_t*>(Oh + (size_t)r * EMB + c) = pack_bf2(h0, h1);
                *reinterpret_cast<uint32_t*>(Ol + (size_t)r * EMB + c) = pack_bf2(l0, l1);
                split_bf(v2, h0, l0); split_bf(v3, h1, l1);
                *reinterpret_cast<uint32_t*>(Oh + (size_t)(r + 8) * EMB + c) = pack_bf2(h0, h1);
                *reinterpret_cast<uint32_t*>(Ol + (size_t)(r + 8) * EMB + c) = pack_bf2(l0, l1);
            }
    }
}

// ---------------- kernel B: E = tf32(exp(mask(QK^T*scale))), rowsum -> g_L --
__global__ __launch_bounds__(256, 1)
void logits_kernel(const void* __restrict__ maskp) {
    __shared__ __align__(16) uint32_t Ah[2][128][12], Al[2][128][12];
    __shared__ __align__(16) uint32_t Bh[2][128][12], Bl[2][128][12];

    const int tid  = threadIdx.x;
    const int warp = tid >> 5, lane = tid & 31;
    const int grp  = lane >> 2, qt = lane & 3;
    const int wm   = (warp >> 2) * 64;
    const int wn   = (warp & 3) * 32;
    const int ib   = blockIdx.x, b = blockIdx.y;
    const int i0   = ib * 128;
    const int lrow = tid >> 1, lhalf = tid & 1;
    const int byteMode = g_mask_mode;

    const __nv_bfloat16* qh = g_Qhi + (size_t)(b * SEQ + i0 + lrow) * EMB + lhalf * 8;
    const __nv_bfloat16* ql = g_Qlo + (size_t)(b * SEQ + i0 + lrow) * EMB + lhalf * 8;

    const uint32_t sAh = smem_u32(&Ah[0][lrow][lhalf * 4]);
    const uint32_t sAl = smem_u32(&Al[0][lrow][lhalf * 4]);
    const uint32_t sBh = smem_u32(&Bh[0][lrow][lhalf * 4]);
    const uint32_t sBl = smem_u32(&Bl[0][lrow][lhalf * 4]);
    const uint32_t bstr = 128 * 12 * 4;

    float rs_priv[4][2] = {};

    for (int jb = 0; jb < 16; ++jb) {
        const int j0 = jb * 128;
        const __nv_bfloat16* kh = g_Khi + (size_t)(b * SEQ + j0 + lrow) * EMB + lhalf * 8;
        const __nv_bfloat16* kl = g_Klo + (size_t)(b * SEQ + j0 + lrow) * EMB + lhalf * 8;

        float acc[4][4][4] = {};

        CP16(sAh, qh); CP16(sAl, ql); CP16(sBh, kh); CP16(sBl, kl);
        CP_COMMIT();

        for (int kt = 0; kt < 64; ++kt) {
            const int buf = kt & 1;
            CP_WAIT0();
            __syncthreads();
            if (kt < 63) {
                const int ko = (kt + 1) * 16;
                const uint32_t bo = (buf ^ 1) * bstr;
                CP16(sAh + bo, qh + ko); CP16(sAl + bo, ql + ko);
                CP16(sBh + bo, kh + ko); CP16(sBl + bo, kl + ko);
                CP_COMMIT();
            }
            uint32_t ah[4][4], al[4][4], bh[4][2], bl[4][2];
            #pragma unroll
            for (int mf = 0; mf < 4; ++mf) {
                const int r = wm + mf * 16 + grp;
                ah[mf][0] = Ah[buf][r][qt];     ah[mf][1] = Ah[buf][r + 8][qt];
                ah[mf][2] = Ah[buf][r][qt + 4]; ah[mf][3] = Ah[buf][r + 8][qt + 4];
                al[mf][0] = Al[buf][r][qt];     al[mf][1] = Al[buf][r + 8][qt];
                al[mf][2] = Al[buf][r][qt + 4]; al[mf][3] = Al[buf][r + 8][qt + 4];
            }
            #pragma unroll
            for (int nf = 0; nf < 4; ++nf) {
                const int n = wn + nf * 8 + grp;
                bh[nf][0] = Bh[buf][n][qt]; bh[nf][1] = Bh[buf][n][qt + 4];
                bl[nf][0] = Bl[buf][n][qt]; bl[nf][1] = Bl[buf][n][qt + 4];
            }
            #pragma unroll
            for (int mf = 0; mf < 4; ++mf)
                #pragma unroll
                for (int nf = 0; nf < 4; ++nf) {
                    mma_bf16(acc[mf][nf], ah[mf], bh[nf]);
                    mma_bf16(acc[mf][nf], al[mf], bh[nf]);
                    mma_bf16(acc[mf][nf], ah[mf], bl[nf]);
                }
        }

        // epilogue: scale, mask, exp, tf32-round, store; accumulate row partials
        #pragma unroll
        for (int mf = 0; mf < 4; ++mf) {
            #pragma unroll
            for (int h = 0; h < 2; ++h) {
                const int rl = wm + mf * 16 + h * 8 + grp;
                const size_t gi = (size_t)(b * SEQ + i0 + rl);
                float rs = 0.f;
                #pragma unroll
                for (int nf = 0; nf < 4; ++nf) {
                    const int gj = j0 + wn + nf * 8 + qt * 2;
                    float s0 = acc[mf][nf][h * 2]     * SCALE;
                    float s1 = acc[mf][nf][h * 2 + 1] * SCALE;
                    bool mk0, mk1;
                    if (byteMode) {
                        const unsigned char* mp = (const unsigned char*)maskp + gi * SEQ + gj;
                        mk0 = mp[0] != 0; mk1 = mp[1] != 0;
                    } else {
                        const int* mp = (const int*)maskp + gi * SEQ + gj;
                        mk0 = mp[0] != 0; mk1 = mp[1] != 0;
                    }
                    float e0 = mk0 ? 0.f : __expf(s0);
                    float e1 = mk1 ? 0.f : __expf(s1);
                    *reinterpret_cast<float2*>(g_S + gi * SEQ + gj) =
                        make_float2(__uint_as_float(f2tf(e0)), __uint_as_float(f2tf(e1)));
                    rs += e0 + e1;
                }
                rs_priv[mf][h] += rs;
            }
        }
    }

    // final row-sum reduction: qt lanes 0..3 hold partials of the same row
    #pragma unroll
    for (int mf = 0; mf < 4; ++mf)
        #pragma unroll
        for (int h = 0; h < 2; ++h) {
            float rs = rs_priv[mf][h];
            rs += __shfl_xor_sync(0xffffffffu, rs, 1);
            rs += __shfl_xor_sync(0xffffffffu, rs, 2);
            if (qt == 0)
                atomicAdd(&g_L[(size_t)b * SEQ + i0 + wm + mf * 16 + h * 8 + grp], rs);
        }
}

// ---------------- att = E * (1/l) ------------------------------------------
__global__ void att_kernel(float* __restrict__ att) {
    const size_t i4 = (size_t)blockIdx.x * blockDim.x + threadIdx.x;
    const size_t base = i4 * 4;
    const int row = (int)(base >> 11);   // SEQ = 2048
    const float l = g_L[row];
    const float il = (l > 0.f) ? __fdividef(1.f, l) : 0.f;
    float4 e = *reinterpret_cast<const float4*>(g_S + base);
    e.x *= il; e.y *= il; e.z *= il; e.w *= il;
    *reinterpret_cast<float4*>(att + base) = e;
}

// ---------------- kernel C: out = (E @ V) * (1/l), tf32 single pass ---------
__global__ __launch_bounds__(256, 1)
void pv_kernel(float* __restrict__ out) {
    __shared__ __align__(16) float Es[2][128][20];
    __shared__ __align__(16) float Vs[2][16][136];
    __shared__ float invl[128];

    const int tid  = threadIdx.x;
    const int warp = tid >> 5, lane = tid & 31;
    const int grp  = lane >> 2, qt = lane & 3;
    const int wm   = (warp >> 2) * 64;
    const int wn   = (warp & 3) * 32;
    const int nch  = blockIdx.x, ib = blockIdx.y, b = blockIdx.z;
    const int i0   = ib * 128, n0 = nch * 128;

    if (tid < 128) {
        const float l = g_L[(size_t)b * SEQ + i0 + tid];
        invl[tid] = (l > 0.f) ? (1.f / l) : 0.f;
    }

    // cp.async staging assignments
    const int er = tid >> 2, eq = tid & 3;     // E: rows er, er+64; 16B chunk eq
    const int vr = tid >> 5, vq = tid & 31;    // V: rows vr, vr+8;  16B chunk vq

    const float* pe0 = g_S + (size_t)(b * SEQ + i0 + er) * SEQ + eq * 4;
    const float* pe1 = g_S + (size_t)(b * SEQ + i0 + 64 + er) * SEQ + eq * 4;
    const float* pv0 = g_V + (size_t)(b * SEQ + vr) * EMB + n0 + vq * 4;
    const float* pv1 = g_V + (size_t)(b * SEQ + 8 + vr) * EMB + n0 + vq * 4;

    const uint32_t sE0 = smem_u32(&Es[0][er][eq * 4]);
    const uint32_t sE1 = smem_u32(&Es[0][64 + er][eq * 4]);
    const uint32_t sV0 = smem_u32(&Vs[0][vr][vq * 4]);
    const uint32_t sV1 = smem_u32(&Vs[0][8 + vr][vq * 4]);
    const uint32_t estr = 128 * 20 * 4;
    const uint32_t vstr = 16 * 136 * 4;

    float acc[4][4][4] = {};

    // prologue: tile jt=0
    CP16(sE0, pe0); CP16(sE1, pe1);
    CP16(sV0, pv0); CP16(sV1, pv1);
    CP_COMMIT();

    for (int jt = 0; jt < 128; ++jt) {
        const int buf = jt & 1;
        CP_WAIT0();
        __syncthreads();
        if (jt < 127) {
            const int jo = (jt + 1) * 16;
            const uint32_t eo = (buf ^ 1) * estr;
            const uint32_t vo = (buf ^ 1) * vstr;
            CP16(sE0 + eo, pe0 + jo);
            CP16(sE1 + eo, pe1 + jo);
            CP16(sV0 + vo, pv0 + (size_t)jo * EMB);
            CP16(sV1 + vo, pv1 + (size_t)jo * EMB);
            CP_COMMIT();
        }
        #pragma unroll
        for (int ks = 0; ks < 2; ++ks) {
            const int kb = ks * 8;
            uint32_t a[4][4], bb[4][2];
            #pragma unroll
            for (int mf = 0; mf < 4; ++mf) {
                const int r = wm + mf * 16 + grp;
                a[mf][0] = __float_as_uint(Es[buf][r][kb + qt]);
                a[mf][1] = __float_as_uint(Es[buf][r + 8][kb + qt]);
                a[mf][2] = __float_as_uint(Es[buf][r][kb + qt + 4]);
                a[mf][3] = __float_as_uint(Es[buf][r + 8][kb + qt + 4]);
            }
            #pragma unroll
            for (int nf = 0; nf < 4; ++nf) {
                const int n = wn + nf * 8 + grp;
                bb[nf][0] = __float_as_uint(Vs[buf][kb + qt][n]);
                bb[nf][1] = __float_as_uint(Vs[buf][kb + qt + 4][n]);
            }
            #pragma unroll
            for (int mf = 0; mf < 4; ++mf)
                #pragma unroll
                for (int nf = 0; nf < 4; ++nf)
                    mma_tf32(acc[mf][nf], a[mf], bb[nf]);
        }
    }

    #pragma unroll
    for (int mf = 0; mf < 4; ++mf)
        #pragma unroll
        for (int nf = 0; nf < 4; ++nf) {
            const int rl = wm + mf * 16 + grp;
            const int r = i0 + rl;
            const int c = n0 + wn + nf * 8 + qt * 2;
            const float il0 = invl[rl], il1 = invl[rl + 8];
            *reinterpret_cast<float2*>(out + (size_t)(b * SEQ + r) * EMB + c) =
                make_float2(acc[mf][nf][0] * il0, acc[mf][nf][1] * il0);
            *reinterpret_cast<float2*>(out + (size_t)(b * SEQ + r + 8) * EMB + c) =
                make_float2(acc[mf][nf][2] * il1, acc[mf][nf][3] * il1);
        }
}

// ---------------- launch -----------------------------------------------------
extern "C" void kernel_launch(void* const* d_in, const int* in_sizes, int n_in,
                              void* d_out, int out_size) {
    const float* x    = (const float*)d_in[0];
    const float* ctx  = (const float*)d_in[1];
    const void*  mask = d_in[2];
    const float* Wq   = (const float*)d_in[3];
    const float* bq   = (const float*)d_in[4];
    const float* Wk   = (const float*)d_in[5];
    const float* bk   = (const float*)d_in[6];
    const float* Wv   = (const float*)d_in[7];
    const float* bv   = (const float*)d_in[8];

    float* out = (float*)d_out;
    float* att = out + (size_t)BATCH * SEQ * EMB;

    detect_mask_kernel<<<1, 32>>>((const unsigned int*)mask);

    const int n4x = BATCH * SEQ * EMB / 4;   // 4,194,304
    const int n4w = EMB * EMB / 4;           // 262,144
    split_kernel<<<(n4x + 255) / 256, 256>>>(x,   0, n4x);
    split_kernel<<<(n4x + 255) / 256, 256>>>(ctx, 1, n4x);
    split_kernel<<<(n4w + 255) / 256, 256>>>(Wq,  2, n4w);
    split_kernel<<<(n4w + 255) / 256, 256>>>(Wk,  3, n4w);
    split_kernel<<<(n4w + 255) / 256, 256>>>(Wv,  4, n4w);

    zeroL_kernel<<<BATCH * SEQ / 256, 256>>>();

    dim3 gproj(EMB / 128, (BATCH * SEQ) / 128);   // (8, 128)
    proj_kernel<<<gproj, 256>>>(bq, 0);
    proj_kernel<<<gproj, 256>>>(bk, 1);
    proj_kernel<<<gproj, 256>>>(bv, 2);

    logits_kernel<<<dim3(SEQ / 128, BATCH), 256>>>(mask);

    att_kernel<<<(int)((size_t)BATCH * SEQ * SEQ / 4 / 256), 256>>>(att);

    pv_kernel<<<dim3(EMB / 128, SEQ / 128, BATCH), 256>>>(out);
}

// round 16
// speedup vs baseline: 1.7400x; 1.0249x over previous
#include <cuda_runtime.h>
#include <cuda_bf16.h>
#include <cstdint>

#define BATCH 8
#define SEQ   2048
#define EMB   1024
#define SCALE 0.03125f   // 1/sqrt(1024)

// ---------------- scratch (device globals; no allocation allowed) ----------
__device__ __nv_bfloat16 g_Xhi[BATCH * SEQ * EMB], g_Xlo[BATCH * SEQ * EMB];
__device__ __nv_bfloat16 g_Chi[BATCH * SEQ * EMB], g_Clo[BATCH * SEQ * EMB];
__device__ __nv_bfloat16 g_Wqh[EMB * EMB], g_Wql[EMB * EMB];
__device__ __nv_bfloat16 g_Wkh[EMB * EMB], g_Wkl[EMB * EMB];
__device__ __nv_bfloat16 g_Wvh[EMB * EMB], g_Wvl[EMB * EMB];
__device__ __nv_bfloat16 g_Qhi[BATCH * SEQ * EMB], g_Qlo[BATCH * SEQ * EMB];
__device__ __nv_bfloat16 g_Khi[BATCH * SEQ * EMB], g_Klo[BATCH * SEQ * EMB];
__device__ float g_V[BATCH * SEQ * EMB];            // tf32-prerounded V
__device__ float g_S[(size_t)BATCH * SEQ * SEQ];    // tf32-prerounded exp(masked logits)
__device__ float g_L[BATCH * SEQ];                  // row sums of exp
__device__ int   g_mask_mode;

// ---------------- helpers --------------------------------------------------
__device__ __forceinline__ uint32_t f2tf(float x) {
    uint32_t r;
    asm("cvt.rna.tf32.f32 %0, %1;" : "=r"(r) : "f"(x));
    return r;
}

__device__ __forceinline__ void mma_tf32(float acc[4], const uint32_t a[4], const uint32_t b[2]) {
    asm volatile(
        "mma.sync.aligned.m16n8k8.row.col.f32.tf32.tf32.f32 "
        "{%0,%1,%2,%3}, {%4,%5,%6,%7}, {%8,%9}, {%0,%1,%2,%3};\n"
        : "+f"(acc[0]), "+f"(acc[1]), "+f"(acc[2]), "+f"(acc[3])
        : "r"(a[0]), "r"(a[1]), "r"(a[2]), "r"(a[3]), "r"(b[0]), "r"(b[1]));
}

__device__ __forceinline__ void mma_bf16(float acc[4], const uint32_t a[4], const uint32_t b[2]) {
    asm volatile(
        "mma.sync.aligned.m16n8k16.row.col.f32.bf16.bf16.f32 "
        "{%0,%1,%2,%3}, {%4,%5,%6,%7}, {%8,%9}, {%0,%1,%2,%3};\n"
        : "+f"(acc[0]), "+f"(acc[1]), "+f"(acc[2]), "+f"(acc[3])
        : "r"(a[0]), "r"(a[1]), "r"(a[2]), "r"(a[3]), "r"(b[0]), "r"(b[1]));
}

__device__ __forceinline__ void split_bf(float v, __nv_bfloat16& h, __nv_bfloat16& l) {
    h = __float2bfloat16_rn(v);
    l = __float2bfloat16_rn(v - __bfloat162float(h));
}

__device__ __forceinline__ uint32_t pack_bf2(__nv_bfloat16 a, __nv_bfloat16 b) {
    __nv_bfloat162 t = __halves2bfloat162(a, b);
    return *reinterpret_cast<uint32_t*>(&t);
}

__device__ __forceinline__ uint32_t smem_u32(const void* p) {
    return (uint32_t)__cvta_generic_to_shared(p);
}

#define CP16(dst, src) \
    asm volatile("cp.async.cg.shared.global [%0], [%1], 16;\n" :: "r"(dst), "l"(src))
#define CP_COMMIT() asm volatile("cp.async.commit_group;\n")
#define CP_WAIT0()  asm volatile("cp.async.wait_group 0;\n")
#define CP_WAIT1()  asm volatile("cp.async.wait_group 1;\n")

// per-k-tile stage: 4 arrays (Ah,Al,Bh,Bl) of [128][12] uint32
#define ARR_BYTES   6144u
#define GEMM_STAGE  24576u            // 4 * ARR_BYTES
#define GEMM_SMEM   (3 * 24576)       // 73728
#define PV_ESTAGE   10240u            // Es[128][20] float
#define PV_STAGE    18944u            // + Vs[16][136] float
#define PV_SMEM     (3 * 18944)       // 56832

// ---------------- mask dtype probe -----------------------------------------
__global__ void detect_mask_kernel(const unsigned int* __restrict__ m) {
    if (threadIdx.x == 0 && blockIdx.x == 0) {
        int bm = 0;
        for (int i = 0; i < 1024; ++i)
            if (m[i] > 1u) { bm = 1; break; }
        g_mask_mode = bm;
    }
}

// ---------------- split inputs into bf16 hi/lo pairs -----------------------
__global__ void split_kernel(const float* __restrict__ src, int sel, int n4) {
    int i = blockIdx.x * blockDim.x + threadIdx.x;
    if (i >= n4) return;
    __nv_bfloat16* hi;
    __nv_bfloat16* lo;
    switch (sel) {
        case 0:  hi = g_Xhi; lo = g_Xlo; break;
        case 1:  hi = g_Chi; lo = g_Clo; break;
        case 2:  hi = g_Wqh; lo = g_Wql; break;
        case 3:  hi = g_Wkh; lo = g_Wkl; break;
        default: hi = g_Wvh; lo = g_Wvl; break;
    }
    float4 v = reinterpret_cast<const float4*>(src)[i];
    __nv_bfloat16 h0, l0, h1, l1, h2, l2, h3, l3;
    split_bf(v.x, h0, l0); split_bf(v.y, h1, l1);
    split_bf(v.z, h2, l2); split_bf(v.w, h3, l3);
    reinterpret_cast<uint2*>(hi)[i] = make_uint2(pack_bf2(h0, h1), pack_bf2(h2, h3));
    reinterpret_cast<uint2*>(lo)[i] = make_uint2(pack_bf2(l0, l1), pack_bf2(l2, l3));
}

// ---------------- bf16x2 3-pass fragment compute on one stage buffer --------
__device__ __forceinline__ void gemm_tile_compute(
    const char* stagep, int warp, int lane, float acc[4][4][4])
{
    const uint32_t* Ah = (const uint32_t*)(stagep);
    const uint32_t* Al = (const uint32_t*)(stagep + ARR_BYTES);
    const uint32_t* Bh = (const uint32_t*)(stagep + 2 * ARR_BYTES);
    const uint32_t* Bl = (const uint32_t*)(stagep + 3 * ARR_BYTES);
    const int grp = lane >> 2, qt = lane & 3;
    const int wm = (warp >> 2) * 64;
    const int wn = (warp & 3) * 32;

    uint32_t ah[4][4], al[4][4], bh[4][2], bl[4][2];
    #pragma unroll
    for (int mf = 0; mf < 4; ++mf) {
        const int r = wm + mf * 16 + grp;
        ah[mf][0] = Ah[r * 12 + qt];       ah[mf][1] = Ah[(r + 8) * 12 + qt];
        ah[mf][2] = Ah[r * 12 + qt + 4];   ah[mf][3] = Ah[(r + 8) * 12 + qt + 4];
        al[mf][0] = Al[r * 12 + qt];       al[mf][1] = Al[(r + 8) * 12 + qt];
        al[mf][2] = Al[r * 12 + qt + 4];   al[mf][3] = Al[(r + 8) * 12 + qt + 4];
    }
    #pragma unroll
    for (int nf = 0; nf < 4; ++nf) {
        const int n = wn + nf * 8 + grp;
        bh[nf][0] = Bh[n * 12 + qt]; bh[nf][1] = Bh[n * 12 + qt + 4];
        bl[nf][0] = Bl[n * 12 + qt]; bl[nf][1] = Bl[n * 12 + qt + 4];
    }
    #pragma unroll
    for (int mf = 0; mf < 4; ++mf)
        #pragma unroll
        for (int nf = 0; nf < 4; ++nf) {
            mma_bf16(acc[mf][nf], ah[mf], bh[nf]);
            mma_bf16(acc[mf][nf], al[mf], bh[nf]);
            mma_bf16(acc[mf][nf], ah[mf], bl[nf]);
        }
}

// ---------------- kernel A: projection  C[M,N] = A[M,K] @ W[N,K]^T + bias ---
// one launch per output (which = 0:Q, 1:K, 2:V), exactly as the passing round
__global__ __launch_bounds__(256, 1)
void proj_kernel(const float* __restrict__ bias, int which) {
    extern __shared__ __align__(16) char dsm[];

    const int tid = threadIdx.x;
    const int warp = tid >> 5, lane = tid & 31;
    const int m0 = blockIdx.y * 128, n0 = blockIdx.x * 128;
    const int row = tid >> 1, half = tid & 1;

    const __nv_bfloat16* Ah_g = (which == 0) ? g_Xhi : g_Chi;
    const __nv_bfloat16* Al_g = (which == 0) ? g_Xlo : g_Clo;
    const __nv_bfloat16* Bh_g = (which == 0) ? g_Wqh : (which == 1) ? g_Wkh : g_Wvh;
    const __nv_bfloat16* Bl_g = (which == 0) ? g_Wql : (which == 1) ? g_Wkl : g_Wvl;

    const __nv_bfloat16* pa_h = Ah_g + (size_t)(m0 + row) * EMB + half * 8;
    const __nv_bfloat16* pa_l = Al_g + (size_t)(m0 + row) * EMB + half * 8;
    const __nv_bfloat16* pb_h = Bh_g + (size_t)(n0 + row) * EMB + half * 8;
    const __nv_bfloat16* pb_l = Bl_g + (size_t)(n0 + row) * EMB + half * 8;

    const uint32_t sbase = smem_u32(dsm);
    const uint32_t stoff = (uint32_t)(row * 48 + half * 16);

    float acc[4][4][4] = {};

    // stage k-chunk c into buffer c%3 (one commit group per chunk)
    #define PROJ_STAGE(c) do {                                          \
        const uint32_t t0 = sbase + (uint32_t)((c) % 3) * GEMM_STAGE + stoff; \
        const int ko = (c) * 16;                                        \
        CP16(t0,                 pa_h + ko);                            \
        CP16(t0 + ARR_BYTES,     pa_l + ko);                            \
        CP16(t0 + 2 * ARR_BYTES, pb_h + ko);                            \
        CP16(t0 + 3 * ARR_BYTES, pb_l + ko);                            \
        CP_COMMIT();                                                    \
    } while (0)

    PROJ_STAGE(0); PROJ_STAGE(1);
    for (int g = 0; g < 64; ++g) {
        if (g == 63) { CP_WAIT0(); } else { CP_WAIT1(); }
        __syncthreads();
        if (g + 2 < 64) PROJ_STAGE(g + 2);
        gemm_tile_compute(dsm + (g % 3) * GEMM_STAGE, warp, lane, acc);
    }
    #undef PROJ_STAGE

    // epilogue (identical to passing version)
    const int grp = lane >> 2, qt = lane & 3;
    const int wm = (warp >> 2) * 64, wn = (warp & 3) * 32;
    if (which == 2) {
        #pragma unroll
        for (int mf = 0; mf < 4; ++mf)
            #pragma unroll
            for (int nf = 0; nf < 4; ++nf) {
                const int r = m0 + wm + mf * 16 + grp;
                const int c = n0 + wn + nf * 8 + qt * 2;
                const float b0v = bias[c], b1v = bias[c + 1];
                *reinterpret_cast<float2*>(g_V + (size_t)r * EMB + c) =
                    make_float2(__uint_as_float(f2tf(acc[mf][nf][0] + b0v)),
                                __uint_as_float(f2tf(acc[mf][nf][1] + b1v)));
                *reinterpret_cast<float2*>(g_V + (size_t)(r + 8) * EMB + c) =
                    make_float2(__uint_as_float(f2tf(acc[mf][nf][2] + b0v)),
                                __uint_as_float(f2tf(acc[mf][nf][3] + b1v)));
            }
    } else {
        __nv_bfloat16* Oh = (which == 0) ? g_Qhi : g_Khi;
        __nv_bfloat16* Ol = (which == 0) ? g_Qlo : g_Klo;
        #pragma unroll
        for (int mf = 0; mf < 4; ++mf)
            #pragma unroll
            for (int nf = 0; nf < 4; ++nf) {
                const int r = m0 + wm + mf * 16 + grp;
                const int c = n0 + wn + nf * 8 + qt * 2;
                const float b0v = bias[c], b1v = bias[c + 1];
                float v0 = acc[mf][nf][0] + b0v, v1 = acc[mf][nf][1] + b1v;
                float v2 = acc[mf][nf][2] + b0v, v3 = acc[mf][nf][3] + b1v;
                __nv_bfloat16 h0, l0, h1, l1;
                split_bf(v0, h0, l0); split_bf(v1, h1, l1);
                *reinterpret_cast<uint32_t*>(Oh + (size_t)r * EMB + c) = pack_bf2(h0, h1);
                *reinterpret_cast<uint32_t*>(Ol + (size_t)r * EMB + c) = pack_bf2(l0, l1);
                split_bf(v2, h0, l0); split_bf(v3, h1, l1);
                *reinterpret_cast<uint32_t*>(Oh + (size_t)(r + 8) * EMB + c) = pack_bf2(h0, h1);
                *reinterpret_cast<uint32_t*>(Ol + (size_t)(r + 8) * EMB + c) = pack_bf2(l0, l1);
            }
    }
}

// ---------------- kernel B: E = tf32(exp(mask(QK^T*scale))), rowsum -> g_L --
// monolithic per 128-row block (grid 16 x 8), nested jb loop as in the
// passing version; pipeline restarted per jb with an end-of-jb barrier.
__global__ __launch_bounds__(256, 1)
void logits_kernel(const void* __restrict__ maskp) {
    extern __shared__ __align__(16) char dsm[];
    __shared__ float l_sm[128];

    const int tid = threadIdx.x;
    const int warp = tid >> 5, lane = tid & 31;
    const int i0 = blockIdx.x * 128, b = blockIdx.y;
    const int row = tid >> 1, half = tid & 1;
    const int byteMode = g_mask_mode;

    if (tid < 128) l_sm[tid] = 0.f;

    const __nv_bfloat16* qa_h = g_Qhi + (size_t)(b * SEQ + i0 + row) * EMB + half * 8;
    const __nv_bfloat16* qa_l = g_Qlo + (size_t)(b * SEQ + i0 + row) * EMB + half * 8;

    const uint32_t sbase = smem_u32(dsm);
    const uint32_t stoff = (uint32_t)(row * 48 + half * 16);

    const int grp = lane >> 2, qt = lane & 3;
    const int wm = (warp >> 2) * 64, wn = (warp & 3) * 32;
    float rs_priv[4][2] = {};

    for (int jb = 0; jb < 16; ++jb) {
        const int j0 = jb * 128;
        const __nv_bfloat16* kb_h = g_Khi + (size_t)(b * SEQ + j0 + row) * EMB + half * 8;
        const __nv_bfloat16* kb_l = g_Klo + (size_t)(b * SEQ + j0 + row) * EMB + half * 8;

        #define LOG_STAGE(c) do {                                       \
            const uint32_t t0 = sbase + (uint32_t)((c) % 3) * GEMM_STAGE + stoff; \
            const int ko = (c) * 16;                                    \
            CP16(t0,                 qa_h + ko);                        \
            CP16(t0 + ARR_BYTES,     qa_l + ko);                        \
            CP16(t0 + 2 * ARR_BYTES, kb_h + ko);                        \
            CP16(t0 + 3 * ARR_BYTES, kb_l + ko);                        \
            CP_COMMIT();                                                \
        } while (0)

        float acc[4][4][4] = {};

        LOG_STAGE(0); LOG_STAGE(1);
        for (int g = 0; g < 64; ++g) {
            if (g == 63) { CP_WAIT0(); } else { CP_WAIT1(); }
            __syncthreads();
            if (g + 2 < 64) LOG_STAGE(g + 2);
            gemm_tile_compute(dsm + (g % 3) * GEMM_STAGE, warp, lane, acc);
        }
        #undef LOG_STAGE

        // epilogue: scale, mask, exp, tf32-round, store; accumulate partials
        #pragma unroll
        for (int mf = 0; mf < 4; ++mf) {
            #pragma unroll
            for (int h = 0; h < 2; ++h) {
                const int rl = wm + mf * 16 + h * 8 + grp;
                const size_t gi = (size_t)(b * SEQ + i0 + rl);
                float rs = 0.f;
                #pragma unroll
                for (int nf = 0; nf < 4; ++nf) {
                    const int gj = j0 + wn + nf * 8 + qt * 2;
                    float s0 = acc[mf][nf][h * 2]     * SCALE;
                    float s1 = acc[mf][nf][h * 2 + 1] * SCALE;
                    bool mk0, mk1;
                    if (byteMode) {
                        const unsigned char* mp = (const unsigned char*)maskp + gi * SEQ + gj;
                        mk0 = mp[0] != 0; mk1 = mp[1] != 0;
                    } else {
                        const int* mp = (const int*)maskp + gi * SEQ + gj;
                        mk0 = mp[0] != 0; mk1 = mp[1] != 0;
                    }
                    float e0 = mk0 ? 0.f : __expf(s0);
                    float e1 = mk1 ? 0.f : __expf(s1);
                    *reinterpret_cast<float2*>(g_S + gi * SEQ + gj) =
                        make_float2(__uint_as_float(f2tf(e0)), __uint_as_float(f2tf(e1)));
                    rs += e0 + e1;
                }
                rs_priv[mf][h] += rs;
            }
        }

        // barrier: next jb's two-chunk prologue must not overwrite buffers
        // while any thread is still computing chunk 63 / the epilogue.
        __syncthreads();
    }

    // reduce partials: qt lanes 0..3 hold partials of the same row
    #pragma unroll
    for (int mf = 0; mf < 4; ++mf)
        #pragma unroll
        for (int h = 0; h < 2; ++h) {
            float rs = rs_priv[mf][h];
            rs += __shfl_xor_sync(0xffffffffu, rs, 1);
            rs += __shfl_xor_sync(0xffffffffu, rs, 2);
            if (qt == 0) atomicAdd(&l_sm[wm + mf * 16 + h * 8 + grp], rs);
        }
    __syncthreads();
    if (tid < 128) g_L[(size_t)b * SEQ + i0 + tid] = l_sm[tid];
}

// ---------------- att = E * (1/l) ------------------------------------------
__global__ void att_kernel(float* __restrict__ att) {
    const size_t i4 = (size_t)blockIdx.x * blockDim.x + threadIdx.x;
    const size_t base = i4 * 4;
    const int row = (int)(base >> 11);   // SEQ = 2048
    const float l = g_L[row];
    const float il = (l > 0.f) ? __fdividef(1.f, l) : 0.f;
    float4 e = *reinterpret_cast<const float4*>(g_S + base);
    e.x *= il; e.y *= il; e.z *= il; e.w *= il;
    *reinterpret_cast<float4*>(att + base) = e;
}

// ---------------- kernel C: out = (E @ V) * (1/l), tf32 single pass ---------
__global__ __launch_bounds__(256, 1)
void pv_kernel(float* __restrict__ out) {
    extern __shared__ __align__(16) char dsm[];
    __shared__ float invl[128];

    const int tid  = threadIdx.x;
    const int warp = tid >> 5, lane = tid & 31;
    const int grp  = lane >> 2, qt = lane & 3;
    const int wm   = (warp >> 2) * 64;
    const int wn   = (warp & 3) * 32;
    const int nch  = blockIdx.x, ib = blockIdx.y, b = blockIdx.z;
    const int i0   = ib * 128, n0 = nch * 128;

    if (tid < 128) {
        const float l = g_L[(size_t)b * SEQ + i0 + tid];
        invl[tid] = (l > 0.f) ? (1.f / l) : 0.f;
    }

    const int er = tid >> 2, eq = tid & 3;
    const int vr = tid >> 5, vq = tid & 31;

    const float* pe0 = g_S + (size_t)(b * SEQ + i0 + er) * SEQ + eq * 4;
    const float* pe1 = g_S + (size_t)(b * SEQ + i0 + 64 + er) * SEQ + eq * 4;
    const float* pv0 = g_V + (size_t)(b * SEQ + vr) * EMB + n0 + vq * 4;
    const float* pv1 = g_V + (size_t)(b * SEQ + 8 + vr) * EMB + n0 + vq * 4;

    const uint32_t sbase = smem_u32(dsm);
    const uint32_t eo0 = (uint32_t)(er * 80 + eq * 16);
    const uint32_t eo1 = (uint32_t)((64 + er) * 80 + eq * 16);
    const uint32_t vo0 = PV_ESTAGE + (uint32_t)(vr * 544 + vq * 16);
    const uint32_t vo1 = PV_ESTAGE + (uint32_t)((8 + vr) * 544 + vq * 16);

    #define PV_STAGE_DO(c) do {                                         \
        const uint32_t t0 = sbase + (uint32_t)((c) % 3) * PV_STAGE;     \
        const int jo = (c) * 16;                                        \
        CP16(t0 + eo0, pe0 + jo);                                       \
        CP16(t0 + eo1, pe1 + jo);                                       \
        CP16(t0 + vo0, pv0 + (size_t)jo * EMB);                         \
        CP16(t0 + vo1, pv1 + (size_t)jo * EMB);                         \
        CP_COMMIT();                                                    \
    } while (0)

    float acc[4][4][4] = {};

    PV_STAGE_DO(0); PV_STAGE_DO(1);
    for (int jt = 0; jt < 128; ++jt) {
        if (jt == 127) { CP_WAIT0(); } else { CP_WAIT1(); }
        __syncthreads();
        if (jt + 2 < 128) PV_STAGE_DO(jt + 2);

        const float* Es = (const float*)(dsm + (jt % 3) * PV_STAGE);
        const float* Vs = Es + PV_ESTAGE / 4;
        #pragma unroll
        for (int ks = 0; ks < 2; ++ks) {
            const int kb = ks * 8;
            uint32_t a[4][4], bb[4][2];
            #pragma unroll
            for (int mf = 0; mf < 4; ++mf) {
                const int r = wm + mf * 16 + grp;
                a[mf][0] = __float_as_uint(Es[r * 20 + kb + qt]);
                a[mf][1] = __float_as_uint(Es[(r + 8) * 20 + kb + qt]);
                a[mf][2] = __float_as_uint(Es[r * 20 + kb + qt + 4]);
                a[mf][3] = __float_as_uint(Es[(r + 8) * 20 + kb + qt + 4]);
            }
            #pragma unroll
            for (int nf = 0; nf < 4; ++nf) {
                const int n = wn + nf * 8 + grp;
                bb[nf][0] = __float_as_uint(Vs[(kb + qt) * 136 + n]);
                bb[nf][1] = __float_as_uint(Vs[(kb + qt + 4) * 136 + n]);
            }
            #pragma unroll
            for (int mf = 0; mf < 4; ++mf)
                #pragma unroll
                for (int nf = 0; nf < 4; ++nf)
                    mma_tf32(acc[mf][nf], a[mf], bb[nf]);
        }
    }
    #undef PV_STAGE_DO

    #pragma unroll
    for (int mf = 0; mf < 4; ++mf)
        #pragma unroll
        for (int nf = 0; nf < 4; ++nf) {
            const int rl = wm + mf * 16 + grp;
            const int r = i0 + rl;
            const int c = n0 + wn + nf * 8 + qt * 2;
            const float il0 = invl[rl], il1 = invl[rl + 8];
            *reinterpret_cast<float2*>(out + (size_t)(b * SEQ + r) * EMB + c) =
                make_float2(acc[mf][nf][0] * il0, acc[mf][nf][1] * il0);
            *reinterpret_cast<float2*>(out + (size_t)(b * SEQ + r + 8) * EMB + c) =
                make_float2(acc[mf][nf][2] * il1, acc[mf][nf][3] * il1);
        }
}

// ---------------- launch -----------------------------------------------------
extern "C" void kernel_launch(void* const* d_in, const int* in_sizes, int n_in,
                              void* d_out, int out_size) {
    const float* x    = (const float*)d_in[0];
    const float* ctx  = (const float*)d_in[1];
    const void*  mask = d_in[2];
    const float* Wq   = (const float*)d_in[3];
    const float* bq   = (const float*)d_in[4];
    const float* Wk   = (const float*)d_in[5];
    const float* bk   = (const float*)d_in[6];
    const float* Wv   = (const float*)d_in[7];
    const float* bv   = (const float*)d_in[8];

    float* out = (float*)d_out;
    float* att = out + (size_t)BATCH * SEQ * EMB;

    // set every call (cheap, immediate API; no static guards allowed)
    cudaFuncSetAttribute(proj_kernel,
                         cudaFuncAttributeMaxDynamicSharedMemorySize, GEMM_SMEM);
    cudaFuncSetAttribute(logits_kernel,
                         cudaFuncAttributeMaxDynamicSharedMemorySize, GEMM_SMEM);
    cudaFuncSetAttribute(pv_kernel,
                         cudaFuncAttributeMaxDynamicSharedMemorySize, PV_SMEM);

    detect_mask_kernel<<<1, 32>>>((const unsigned int*)mask);

    const int n4x = BATCH * SEQ * EMB / 4;
    const int n4w = EMB * EMB / 4;
    split_kernel<<<(n4x + 255) / 256, 256>>>(x,   0, n4x);
    split_kernel<<<(n4x + 255) / 256, 256>>>(ctx, 1, n4x);
    split_kernel<<<(n4w + 255) / 256, 256>>>(Wq,  2, n4w);
    split_kernel<<<(n4w + 255) / 256, 256>>>(Wk,  3, n4w);
    split_kernel<<<(n4w + 255) / 256, 256>>>(Wv,  4, n4w);

    dim3 gproj(EMB / 128, (BATCH * SEQ) / 128);   // (8, 128)
    proj_kernel<<<gproj, 256, GEMM_SMEM>>>(bq, 0);
    proj_kernel<<<gproj, 256, GEMM_SMEM>>>(bk, 1);
    proj_kernel<<<gproj, 256, GEMM_SMEM>>>(bv, 2);

    logits_kernel<<<dim3(SEQ / 128, BATCH), 256, GEMM_SMEM>>>(mask);

    att_kernel<<<(int)((size_t)BATCH * SEQ * SEQ / 4 / 256), 256>>>(att);

    pv_kernel<<<dim3(EMB / 128, SEQ / 128, BATCH), 256, PV_SMEM>>>(out);
}